// round 12
// baseline (speedup 1.0000x reference)
#include <cuda_runtime.h>

// ConstrainNet residual:
//   out[0:64]            = V[0,:64] - x0
//   out[t*64 : t*64+64]  = [A B] @ V[t-1] - V[t,:64]   for t = 1..T-1
// Shapes: A (64,64), B (64,32), x0 (64), net_input = V (T=128, 96), out (T*64,)
//
// 32 CTAs x 256 threads, thread = (s, kq) with kq a 4-way split of the
// 96-wide dot (24 floats each). Each thread stages its 24-float AB segment
// ONCE (6 LDG.128) and reuses it for FOUR timesteps: four independent
// 24-FMA/4-acc chains, then two shfl_xor levels (1, 2) combine quarters.
// ~110 regs (vs 255/spilling at the 2-way split). No smem, no barriers.

constexpr int NS = 64;
constexpr int NA = 96;
constexpr int T  = 128;
constexpr int BT = 4;
constexpr int THREADS = 256;   // 64 rows * 4 k-quarters

__global__ __launch_bounds__(THREADS, 1)
void constrainnet_kernel(const float* __restrict__ A,
                         const float* __restrict__ B,
                         const float* __restrict__ x0,
                         const float* __restrict__ V,
                         float* __restrict__ out) {
    const unsigned tid = threadIdx.x;
    const unsigned s   = tid >> 2;     // output row
    const unsigned kq  = tid & 3;      // k-quarter: [24*kq, 24*kq+24)
    const int t0 = (int)(blockIdx.x * BT);

    // Loads gating the final subtracts: issue immediately.
    float vts[BT];
    #pragma unroll
    for (int g = 0; g < BT; ++g)
        vts[g] = __ldg(&V[(t0 + g) * NA + s]);
    const float x0s = (t0 == 0) ? __ldg(&x0[s]) : 0.0f;

    // AB row s, k-segment [24*kq, 24*kq+24), as two float4 base pointers
    // (p0: 4 vecs, p1: 2 vecs) to handle the kq=2 A/B straddle:
    //   kq=0: A[s][ 0:16) | A[s][16:24)
    //   kq=1: A[s][24:40) | A[s][40:48)
    //   kq=2: A[s][48:64) | B[s][ 0: 8)
    //   kq=3: B[s][ 8:24) | B[s][24:32)
    const float* Arow = A + s * 64;
    const float* Brow = B + s * 32;
    const float4* P0;
    const float4* P1;
    if (kq < 2) {
        P0 = reinterpret_cast<const float4*>(Arow + kq * 24);
        P1 = reinterpret_cast<const float4*>(Arow + kq * 24 + 16);
    } else if (kq == 2) {
        P0 = reinterpret_cast<const float4*>(Arow + 48);
        P1 = reinterpret_cast<const float4*>(Brow);
    } else {
        P0 = reinterpret_cast<const float4*>(Brow + 8);
        P1 = reinterpret_cast<const float4*>(Brow + 24);
    }

    // V row pointers for the BT dot products (rows t0-1 .. t0+BT-2), clamped.
    const float4* Vp[BT];
    #pragma unroll
    for (int g = 0; g < BT; ++g) {
        int tp = t0 + g - 1;
        if (tp < 0) tp = 0;            // t==0 result overridden below
        Vp[g] = reinterpret_cast<const float4*>(V + tp * NA + kq * 24);
    }

    // Stage AB segment once (6 independent 128-bit loads, 24 regs).
    float4 ab[6];
    #pragma unroll
    for (int j = 0; j < 4; ++j) ab[j] = P0[j];
    #pragma unroll
    for (int j = 0; j < 2; ++j) ab[4 + j] = P1[j];

    // Four independent 24-FMA dot products sharing the staged AB registers.
    float acc[BT][4];
    #pragma unroll
    for (int g = 0; g < BT; ++g)
        acc[g][0] = acc[g][1] = acc[g][2] = acc[g][3] = 0.0f;

    #pragma unroll
    for (int j = 0; j < 6; ++j) {
        const float4 a = ab[j];
        #pragma unroll
        for (int g = 0; g < BT; ++g) {
            float4 v = Vp[g][j];
            acc[g][0] = fmaf(a.x, v.x, acc[g][0]);
            acc[g][1] = fmaf(a.y, v.y, acc[g][1]);
            acc[g][2] = fmaf(a.z, v.z, acc[g][2]);
            acc[g][3] = fmaf(a.w, v.w, acc[g][3]);
        }
    }

    float r[BT];
    #pragma unroll
    for (int g = 0; g < BT; ++g) {
        float dot = (acc[g][0] + acc[g][1]) + (acc[g][2] + acc[g][3]);
        dot += __shfl_xor_sync(0xFFFFFFFFu, dot, 1);
        dot += __shfl_xor_sync(0xFFFFFFFFu, dot, 2);
        r[g] = dot - vts[g];
    }
    if (t0 == 0) r[0] = vts[0] - x0s;

    if (kq == 0) {
        #pragma unroll
        for (int g = 0; g < BT; ++g)
            out[(t0 + g) * NS + s] = r[g];
    }
}

extern "C" void kernel_launch(void* const* d_in, const int* in_sizes, int n_in,
                              void* d_out, int out_size) {
    const float* A  = (const float*)d_in[0];
    const float* B  = (const float*)d_in[1];
    const float* x0 = (const float*)d_in[2];
    const float* V  = (const float*)d_in[3];
    float* out = (float*)d_out;

    constrainnet_kernel<<<T / BT, THREADS>>>(A, B, x0, V, out);
}

// round 14
// speedup vs baseline: 1.0048x; 1.0048x over previous
#include <cuda_runtime.h>

// ConstrainNet residual:
//   out[0:64]            = V[0,:64] - x0
//   out[t*64 : t*64+64]  = [A B] @ V[t-1] - V[t,:64]   for t = 1..T-1
// Shapes: A (64,64), B (64,32), x0 (64), net_input = V (T=128, 96), out (T*64,)
//
// 64 CTAs x 256 threads (measured-best grid + measured-best split):
// thread = (s, kq), kq a 4-way split of the 96-wide dot (24 floats each).
// Each thread stages its 24-float AB segment ONCE (6 LDG.128) and reuses it
// for BOTH timesteps: two independent 24-FMA/4-acc chains, then two
// shfl_xor levels (1, 2) combine the quarters. No smem, no barriers.

constexpr int NS = 64;
constexpr int NA = 96;
constexpr int T  = 128;
constexpr int BT = 2;
constexpr int THREADS = 256;   // 64 rows * 4 k-quarters

__global__ __launch_bounds__(THREADS, 1)
void constrainnet_kernel(const float* __restrict__ A,
                         const float* __restrict__ B,
                         const float* __restrict__ x0,
                         const float* __restrict__ V,
                         float* __restrict__ out) {
    const unsigned tid = threadIdx.x;
    const unsigned s   = tid >> 2;     // output row
    const unsigned kq  = tid & 3;      // k-quarter: [24*kq, 24*kq+24)
    const int t0 = (int)(blockIdx.x * BT);
    const int t1 = t0 + 1;

    // Loads gating the final subtracts: issue immediately.
    const float vt0s = __ldg(&V[t0 * NA + s]);
    const float vt1s = __ldg(&V[t1 * NA + s]);
    const float x0s  = (t0 == 0) ? __ldg(&x0[s]) : 0.0f;

    // AB row s, k-segment [24*kq, 24*kq+24), two float4 base pointers
    // (P0: 4 vecs, P1: 2 vecs) to handle the kq=2 A/B straddle:
    //   kq=0: A[s][ 0:16) | A[s][16:24)
    //   kq=1: A[s][24:40) | A[s][40:48)
    //   kq=2: A[s][48:64) | B[s][ 0: 8)
    //   kq=3: B[s][ 8:24) | B[s][24:32)
    const float* Arow = A + s * 64;
    const float* Brow = B + s * 32;
    const float4* P0;
    const float4* P1;
    if (kq < 2) {
        P0 = reinterpret_cast<const float4*>(Arow + kq * 24);
        P1 = reinterpret_cast<const float4*>(Arow + kq * 24 + 16);
    } else if (kq == 2) {
        P0 = reinterpret_cast<const float4*>(Arow + 48);
        P1 = reinterpret_cast<const float4*>(Brow);
    } else {
        P0 = reinterpret_cast<const float4*>(Brow + 8);
        P1 = reinterpret_cast<const float4*>(Brow + 24);
    }

    const int tp0 = (t0 > 0) ? (t0 - 1) : 0;   // clamped; t0==0 overridden
    const float4* Vp0 = reinterpret_cast<const float4*>(V + tp0 * NA + kq * 24);
    const float4* Vp1 = reinterpret_cast<const float4*>(V + t0  * NA + kq * 24);

    // Stage AB segment once (6 independent 128-bit loads, 24 regs).
    float4 ab[6];
    #pragma unroll
    for (int j = 0; j < 4; ++j) ab[j] = P0[j];
    #pragma unroll
    for (int j = 0; j < 2; ++j) ab[4 + j] = P1[j];

    // Two independent 24-FMA dot products sharing the staged AB registers.
    float a0 = 0.f, a1 = 0.f, a2 = 0.f, a3 = 0.f;   // t0
    float c0 = 0.f, c1 = 0.f, c2 = 0.f, c3 = 0.f;   // t1
    #pragma unroll
    for (int j = 0; j < 6; ++j) {
        const float4 a = ab[j];
        float4 u = Vp0[j];
        float4 w = Vp1[j];
        a0 = fmaf(a.x, u.x, a0);
        a1 = fmaf(a.y, u.y, a1);
        a2 = fmaf(a.z, u.z, a2);
        a3 = fmaf(a.w, u.w, a3);
        c0 = fmaf(a.x, w.x, c0);
        c1 = fmaf(a.y, w.y, c1);
        c2 = fmaf(a.z, w.z, c2);
        c3 = fmaf(a.w, w.w, c3);
    }
    float dot0 = (a0 + a1) + (a2 + a3);
    float dot1 = (c0 + c1) + (c2 + c3);
    dot0 += __shfl_xor_sync(0xFFFFFFFFu, dot0, 1);
    dot0 += __shfl_xor_sync(0xFFFFFFFFu, dot0, 2);
    dot1 += __shfl_xor_sync(0xFFFFFFFFu, dot1, 1);
    dot1 += __shfl_xor_sync(0xFFFFFFFFu, dot1, 2);

    const float r0 = (t0 == 0) ? (vt0s - x0s) : (dot0 - vt0s);
    const float r1 = dot1 - vt1s;

    if (kq == 0) {
        out[t0 * NS + s] = r0;
        out[t1 * NS + s] = r1;
    }
}

extern "C" void kernel_launch(void* const* d_in, const int* in_sizes, int n_in,
                              void* d_out, int out_size) {
    const float* A  = (const float*)d_in[0];
    const float* B  = (const float*)d_in[1];
    const float* x0 = (const float*)d_in[2];
    const float* V  = (const float*)d_in[3];
    float* out = (float*)d_out;

    constrainnet_kernel<<<T / BT, THREADS>>>(A, B, x0, V, out);
}